// round 2
// baseline (speedup 1.0000x reference)
#include <cuda_runtime.h>
#include <cuda_bf16.h>
#include <math.h>

#define N_NODES   100000
#define N_EDGES   6400000
#define N_FEAT    128
#define HIDDEN    16
#define N_CLASSES 10
#define N_GRAPHS  1024

// ---------------- scratch (device globals; no allocation allowed) ------------
__device__ float g_h0[(size_t)N_NODES * HIDDEN];
__device__ float g_h1[(size_t)N_NODES * HIDDEN];
__device__ float g_agg[(size_t)N_NODES * HIDDEN];
__device__ float g_deg[N_NODES];
__device__ float g_h3[(size_t)N_NODES * N_CLASSES];
__device__ float g_pooled[N_GRAPHS * N_CLASSES];
__device__ float g_cnt[N_GRAPHS];

// ---------------- helpers ----------------------------------------------------
__device__ __forceinline__ void red_add_v4(float4* addr, float4 v) {
    asm volatile("red.global.add.v4.f32 [%0], {%1,%2,%3,%4};"
                 :: "l"(addr), "f"(v.x), "f"(v.y), "f"(v.z), "f"(v.w)
                 : "memory");
}

// ---------------- zero kernels ------------------------------------------------
__global__ void k_zero_agg() {
    int i = blockIdx.x * blockDim.x + threadIdx.x;
    if (i < N_NODES * HIDDEN) g_agg[i] = 0.0f;
}
__global__ void k_zero_misc() {
    int i = blockIdx.x * blockDim.x + threadIdx.x;
    if (i < N_NODES) g_deg[i] = 0.0f;
    if (i < N_GRAPHS * N_CLASSES) g_pooled[i] = 0.0f;
    if (i < N_GRAPHS) g_cnt[i] = 0.0f;
}

// ---------------- 1) argmax over features + embedding lookup ------------------
// one warp per node; lane l reads float4 at column 4l (fully coalesced 512B/warp)
__global__ void k_argmax_embed(const float* __restrict__ x,
                               const float* __restrict__ emb) {
    int warp = (blockIdx.x * blockDim.x + threadIdx.x) >> 5;
    int lane = threadIdx.x & 31;
    if (warp >= N_NODES) return;

    const float4* xp = reinterpret_cast<const float4*>(x + (size_t)warp * N_FEAT);
    float4 v = xp[lane];
    float best = v.x; int bi = lane * 4;
    if (v.y > best) { best = v.y; bi = lane * 4 + 1; }
    if (v.z > best) { best = v.z; bi = lane * 4 + 2; }
    if (v.w > best) { best = v.w; bi = lane * 4 + 3; }

    #pragma unroll
    for (int o = 16; o > 0; o >>= 1) {
        float ov = __shfl_down_sync(0xffffffffu, best, o);
        int   oi = __shfl_down_sync(0xffffffffu, bi,   o);
        if (ov > best || (ov == best && oi < bi)) { best = ov; bi = oi; }
    }
    bi = __shfl_sync(0xffffffffu, bi, 0);

    if (lane < HIDDEN)
        g_h0[(size_t)warp * HIDDEN + lane] = emb[bi * HIDDEN + lane];
}

// ---------------- 2) edge scatter: agg[dst] += h[src] -------------------------
// in_sel: 0 -> g_h0, 1 -> g_h1.  add_deg: accumulate degree on first pass.
__global__ void k_scatter(const int* __restrict__ src,
                          const int* __restrict__ dst,
                          int in_sel, int add_deg) {
    int e = blockIdx.x * blockDim.x + threadIdx.x;
    if (e >= N_EDGES) return;
    int s = __ldg(&src[e]);
    int d = __ldg(&dst[e]);

    const float* h = in_sel ? g_h1 : g_h0;
    const float4* hp = reinterpret_cast<const float4*>(h + (size_t)s * HIDDEN);
    float4 v0 = hp[0], v1 = hp[1], v2 = hp[2], v3 = hp[3];

    float4* ap = reinterpret_cast<float4*>(g_agg + (size_t)d * HIDDEN);
    red_add_v4(ap + 0, v0);
    red_add_v4(ap + 1, v1);
    red_add_v4(ap + 2, v2);
    red_add_v4(ap + 3, v3);

    if (add_deg) atomicAdd(&g_deg[d], 1.0f);
}

// ---------------- 3) per-node transform: Wl@(agg/deg) + b + Wr@h, L2-norm -----
// in_sel: 0->g_h0, 1->g_h1 ;  out_sel: 0->g_h0, 1->g_h1, 2->g_h3
template<int HOUT, bool RELU>
__global__ void k_node(const float* __restrict__ Wl, const float* __restrict__ b,
                       const float* __restrict__ Wr, int in_sel, int out_sel) {
    __shared__ float sWl[HOUT * HIDDEN];
    __shared__ float sWr[HOUT * HIDDEN];
    __shared__ float sb[HOUT];
    for (int t = threadIdx.x; t < HOUT * HIDDEN; t += blockDim.x) {
        sWl[t] = Wl[t];
        sWr[t] = Wr[t];
    }
    if (threadIdx.x < HOUT) sb[threadIdx.x] = b[threadIdx.x];
    __syncthreads();

    int i = blockIdx.x * blockDim.x + threadIdx.x;
    if (i >= N_NODES) return;

    const float* h = in_sel ? g_h1 : g_h0;
    float inv = 1.0f / fmaxf(g_deg[i], 1.0f);

    float a[HIDDEN], hh[HIDDEN];
    const float4* ap = reinterpret_cast<const float4*>(g_agg + (size_t)i * HIDDEN);
    const float4* hp = reinterpret_cast<const float4*>(h     + (size_t)i * HIDDEN);
    #pragma unroll
    for (int q = 0; q < 4; q++) {
        float4 av = ap[q], hv = hp[q];
        a[q*4+0] = av.x * inv; a[q*4+1] = av.y * inv;
        a[q*4+2] = av.z * inv; a[q*4+3] = av.w * inv;
        hh[q*4+0] = hv.x; hh[q*4+1] = hv.y; hh[q*4+2] = hv.z; hh[q*4+3] = hv.w;
    }

    float o[HOUT];
    float nrm = 0.0f;
    #pragma unroll
    for (int c = 0; c < HOUT; c++) {
        float acc = sb[c];
        #pragma unroll
        for (int j = 0; j < HIDDEN; j++)
            acc = fmaf(a[j], sWl[c * HIDDEN + j], fmaf(hh[j], sWr[c * HIDDEN + j], acc));
        o[c] = acc;
        nrm += acc * acc;
    }
    float inv_n = 1.0f / fmaxf(sqrtf(nrm), 1e-12f);

    float* outp = (out_sel == 0) ? g_h0 : (out_sel == 1) ? g_h1 : g_h3;
    #pragma unroll
    for (int c = 0; c < HOUT; c++) {
        float val = o[c] * inv_n;
        if (RELU) val = fmaxf(val, 0.0f);
        outp[(size_t)i * HOUT + c] = val;
    }
}

// ---------------- 4) global mean pool (segment sums via atomics) --------------
__global__ void k_pool(const int* __restrict__ batch) {
    int i = blockIdx.x * blockDim.x + threadIdx.x;
    if (i >= N_NODES) return;
    int g = __ldg(&batch[i]);
    const float* row = g_h3 + (size_t)i * N_CLASSES;
    #pragma unroll
    for (int c = 0; c < N_CLASSES; c++)
        atomicAdd(&g_pooled[g * N_CLASSES + c], row[c]);
    atomicAdd(&g_cnt[g], 1.0f);
}

// ---------------- 5) mean + softmax -------------------------------------------
__global__ void k_softmax(float* __restrict__ out) {
    int g = blockIdx.x * blockDim.x + threadIdx.x;
    if (g >= N_GRAPHS) return;
    float inv = 1.0f / fmaxf(g_cnt[g], 1.0f);
    float v[N_CLASSES];
    float mx = -INFINITY;
    #pragma unroll
    for (int c = 0; c < N_CLASSES; c++) {
        v[c] = g_pooled[g * N_CLASSES + c] * inv;
        mx = fmaxf(mx, v[c]);
    }
    float s = 0.0f;
    #pragma unroll
    for (int c = 0; c < N_CLASSES; c++) { v[c] = expf(v[c] - mx); s += v[c]; }
    float inv_s = 1.0f / s;
    #pragma unroll
    for (int c = 0; c < N_CLASSES; c++)
        out[g * N_CLASSES + c] = v[c] * inv_s;
}

// ---------------- launch ------------------------------------------------------
extern "C" void kernel_launch(void* const* d_in, const int* in_sizes, int n_in,
                              void* d_out, int out_size) {
    const float* x     = (const float*)d_in[0];
    const int*   ei    = (const int*)d_in[1];   // [2, E] int32 (JAX x64 disabled)
    const int*   batch = (const int*)d_in[2];
    const float* emb   = (const float*)d_in[3];
    const float* W1l   = (const float*)d_in[4];
    const float* b1    = (const float*)d_in[5];
    const float* W1r   = (const float*)d_in[6];
    const float* W2l   = (const float*)d_in[7];
    const float* b2    = (const float*)d_in[8];
    const float* W2r   = (const float*)d_in[9];
    const float* W3l   = (const float*)d_in[10];
    const float* b3    = (const float*)d_in[11];
    const float* W3r   = (const float*)d_in[12];
    float* out = (float*)d_out;

    const int* src = ei;
    const int* dst = ei + N_EDGES;

    const int TB = 256;
    const int gb_agg  = (N_NODES * HIDDEN + TB - 1) / TB;
    const int gb_node = (N_NODES + TB - 1) / TB;
    const int gb_edge = (N_EDGES + TB - 1) / TB;
    const int gb_warp = (N_NODES * 32 + TB - 1) / TB;

    // init
    k_zero_agg<<<gb_agg, TB>>>();
    k_zero_misc<<<gb_node, TB>>>();

    // embedding
    k_argmax_embed<<<gb_warp, TB>>>(x, emb);

    // conv 1 (h0 -> h1), degree computed here
    k_scatter<<<gb_edge, TB>>>(src, dst, /*in_sel=*/0, /*add_deg=*/1);
    k_node<HIDDEN, true><<<gb_node, TB>>>(W1l, b1, W1r, /*in=*/0, /*out=*/1);

    // conv 2 (h1 -> h0)
    k_zero_agg<<<gb_agg, TB>>>();
    k_scatter<<<gb_edge, TB>>>(src, dst, /*in_sel=*/1, /*add_deg=*/0);
    k_node<HIDDEN, true><<<gb_node, TB>>>(W2l, b2, W2r, /*in=*/1, /*out=*/0);

    // conv 3 (h0 -> h3[N,10])
    k_zero_agg<<<gb_agg, TB>>>();
    k_scatter<<<gb_edge, TB>>>(src, dst, /*in_sel=*/0, /*add_deg=*/0);
    k_node<N_CLASSES, false><<<gb_node, TB>>>(W3l, b3, W3r, /*in=*/0, /*out=*/2);

    // pool + softmax
    k_pool<<<gb_node, TB>>>(batch);
    k_softmax<<<(N_GRAPHS + TB - 1) / TB, TB>>>(out);
}